// round 1
// baseline (speedup 1.0000x reference)
#include <cuda_runtime.h>
#include <math.h>

// Fixed problem shape (SimpleLanguageModel_65498251264578)
#define BB 2
#define TT 2048
#define HH 1024
#define VV 32000
#define LL 4
#define BT (BB * TT)   // 4096

// ---------------------------------------------------------------------------
// Scratch (device globals — allocation-free rule)
// ---------------------------------------------------------------------------
__device__ float g_x[BT * HH];                    // embeddings
__device__ float g_q[BT * HH];
__device__ float g_k[BT * HH];
__device__ float g_v[BT * HH];
__device__ float g_s[BB * TT * TT];               // attention scores / probs
__device__ float g_a[BT * HH];                    // attn out / mlp ping
__device__ float g_b[BT * HH];                    // mlp pong
__device__ float g_rowloss[BT];
__device__ float g_logits_fb[BT * VV];            // fallback if d_out is loss-only

// ---------------------------------------------------------------------------
// Embedding: x[b,t,:] = tok_emb[idx[b,t],:] + pos_emb[t,:]
// ---------------------------------------------------------------------------
__global__ void embed_k(const int* __restrict__ idx,
                        const float* __restrict__ tok,
                        const float* __restrict__ pos,
                        float* __restrict__ x) {
    int bt = blockIdx.x;
    int t = bt % TT;
    int v = idx[bt];
    const float* te = tok + (long long)v * HH;
    const float* pe = pos + (long long)t * HH;
    float* xo = x + (long long)bt * HH;
    for (int h = threadIdx.x; h < HH; h += blockDim.x)
        xo[h] = te[h] + pe[h];
}

// ---------------------------------------------------------------------------
// SGEMM: C = act(alpha * A @ op(B) + bias)
//   A: [M,K] row-major.  TB=false: B [K,N] row-major.  TB=true: B [N,K] (C=A@B^T)
//   128x128 block tile, BK=8, 256 threads, 8x8 per-thread microtile.
//   All dims must be multiples of the tile (true for every call here).
//   blockIdx.z batches with strides sA/sB/sC.
// ---------------------------------------------------------------------------
template <bool TB, bool LEAKY>
__global__ void __launch_bounds__(256, 2) sgemm_k(
    const float* __restrict__ A, const float* __restrict__ B,
    const float* __restrict__ bias, float* __restrict__ C,
    int M, int N, int K, float alpha,
    long long sA, long long sB, long long sC) {
    A += (long long)blockIdx.z * sA;
    B += (long long)blockIdx.z * sB;
    C += (long long)blockIdx.z * sC;

    __shared__ float As[8][128];
    __shared__ float Bs[8][128];

    const int tid = threadIdx.x;
    const int m0 = blockIdx.y * 128;
    const int n0 = blockIdx.x * 128;
    const int tx = tid & 15;    // 0..15 -> 8 cols each
    const int ty = tid >> 4;    // 0..15 -> 8 rows each

    // global->smem load mapping
    const int arow = tid >> 1;          // 0..127
    const int acol = (tid & 1) << 2;    // 0 or 4
    const int brow = tid >> 5;          // 0..7   (NN)
    const int bcol = (tid & 31) << 2;   // 0..124 (NN)

    float acc[8][8];
#pragma unroll
    for (int i = 0; i < 8; i++)
#pragma unroll
        for (int j = 0; j < 8; j++) acc[i][j] = 0.f;

    for (int k0 = 0; k0 < K; k0 += 8) {
        float4 av = *(const float4*)(A + (long long)(m0 + arow) * K + (k0 + acol));
        As[acol + 0][arow] = av.x;
        As[acol + 1][arow] = av.y;
        As[acol + 2][arow] = av.z;
        As[acol + 3][arow] = av.w;
        if (!TB) {
            float4 bv = *(const float4*)(B + (long long)(k0 + brow) * N + (n0 + bcol));
            *(float4*)&Bs[brow][bcol] = bv;
        } else {
            float4 bv = *(const float4*)(B + (long long)(n0 + arow) * K + (k0 + acol));
            Bs[acol + 0][arow] = bv.x;
            Bs[acol + 1][arow] = bv.y;
            Bs[acol + 2][arow] = bv.z;
            Bs[acol + 3][arow] = bv.w;
        }
        __syncthreads();
#pragma unroll
        for (int kk = 0; kk < 8; kk++) {
            float a[8], b[8];
            *(float4*)&a[0] = *(const float4*)&As[kk][ty * 8];
            *(float4*)&a[4] = *(const float4*)&As[kk][ty * 8 + 4];
            *(float4*)&b[0] = *(const float4*)&Bs[kk][tx * 8];
            *(float4*)&b[4] = *(const float4*)&Bs[kk][tx * 8 + 4];
#pragma unroll
            for (int i = 0; i < 8; i++)
#pragma unroll
                for (int j = 0; j < 8; j++)
                    acc[i][j] = fmaf(a[i], b[j], acc[i][j]);
        }
        __syncthreads();
    }

#pragma unroll
    for (int i = 0; i < 8; i++) {
        int m = m0 + ty * 8 + i;
        float* crow = C + (long long)m * N + n0 + tx * 8;
        float4 c0, c1;
        float cc[8];
#pragma unroll
        for (int j = 0; j < 8; j++) {
            float c = acc[i][j] * alpha;
            if (bias) c += bias[n0 + tx * 8 + j];
            if (LEAKY) c = (c >= 0.f) ? c : 0.01f * c;
            cc[j] = c;
        }
        c0 = make_float4(cc[0], cc[1], cc[2], cc[3]);
        c1 = make_float4(cc[4], cc[5], cc[6], cc[7]);
        *(float4*)crow = c0;
        *(float4*)(crow + 4) = c1;
    }
}

// ---------------------------------------------------------------------------
// Reductions
// ---------------------------------------------------------------------------
__device__ __forceinline__ float block_max(float v, float* red) {
    int tid = threadIdx.x;
    red[tid] = v;
    __syncthreads();
    for (int s = 128; s > 0; s >>= 1) {
        if (tid < s) red[tid] = fmaxf(red[tid], red[tid + s]);
        __syncthreads();
    }
    float r = red[0];
    __syncthreads();
    return r;
}

__device__ __forceinline__ float block_sum(float v, float* red) {
    int tid = threadIdx.x;
    red[tid] = v;
    __syncthreads();
    for (int s = 128; s > 0; s >>= 1) {
        if (tid < s) red[tid] += red[tid + s];
        __syncthreads();
    }
    float r = red[0];
    __syncthreads();
    return r;
}

// Causal softmax over scores in-place. One block per (b, query-row).
__global__ void softmax_causal_k(float* __restrict__ s) {
    __shared__ float red[256];
    long long row = blockIdx.x;     // 0..BB*TT-1
    int r = (int)(row % TT);        // query position
    float* p = s + row * (long long)TT;
    int n = r + 1;                  // valid (unmasked) length
    int tid = threadIdx.x;

    float mx = -INFINITY;
    for (int j = tid; j < n; j += 256) mx = fmaxf(mx, p[j]);
    mx = block_max(mx, red);

    float sum = 0.f;
    for (int j = tid; j < n; j += 256) sum += expf(p[j] - mx);
    sum = block_sum(sum, red);
    float inv = 1.f / sum;

    for (int j = tid; j < n; j += 256) p[j] = expf(p[j] - mx) * inv;
    for (int j = n + tid; j < TT; j += 256) p[j] = 0.f;
}

// Per-row cross entropy: rowloss[r] = max + log(sum exp(logit-max)) - logit[target]
__global__ void ce_row_k(const float* __restrict__ logits,
                         const int* __restrict__ targets,
                         float* __restrict__ rowloss) {
    __shared__ float red[256];
    int row = blockIdx.x;
    const float* p = logits + (long long)row * VV;
    int tid = threadIdx.x;

    float mx = -INFINITY;
    for (int j = tid; j < VV; j += 256) mx = fmaxf(mx, p[j]);
    mx = block_max(mx, red);

    float sum = 0.f;
    for (int j = tid; j < VV; j += 256) sum += expf(p[j] - mx);
    sum = block_sum(sum, red);

    if (tid == 0)
        rowloss[row] = mx + logf(sum) - p[targets[row]];
}

__global__ void loss_reduce_k(const float* __restrict__ rowloss,
                              float* __restrict__ out) {
    __shared__ float red[256];
    int tid = threadIdx.x;
    float s = 0.f;
    for (int j = tid; j < BT; j += 256) s += rowloss[j];
    s = block_sum(s, red);
    if (tid == 0) out[0] = s / (float)BT;
}

// ---------------------------------------------------------------------------
// Launch
// ---------------------------------------------------------------------------
extern "C" void kernel_launch(void* const* d_in, const int* in_sizes, int n_in,
                              void* d_out, int out_size) {
    const int* idx = (const int*)d_in[0];
    const int* tgt = (const int*)d_in[1];
    const float* tok = (const float*)d_in[2];
    const float* pos = (const float*)d_in[3];
    const float* wq = (const float*)d_in[4];
    const float* wk = (const float*)d_in[5];
    const float* wv = (const float*)d_in[6];
    const float* hw = (const float*)d_in[7];
    const float* hb = (const float*)d_in[8];
    const float* lw = (const float*)d_in[9];
    const float* lb = (const float*)d_in[10];

    float *x, *q, *k, *v, *s, *a, *b, *rl, *fb;
    cudaGetSymbolAddress((void**)&x, g_x);
    cudaGetSymbolAddress((void**)&q, g_q);
    cudaGetSymbolAddress((void**)&k, g_k);
    cudaGetSymbolAddress((void**)&v, g_v);
    cudaGetSymbolAddress((void**)&s, g_s);
    cudaGetSymbolAddress((void**)&a, g_a);
    cudaGetSymbolAddress((void**)&b, g_b);
    cudaGetSymbolAddress((void**)&rl, g_rowloss);
    cudaGetSymbolAddress((void**)&fb, g_logits_fb);

    float* out = (float*)d_out;
    const long long btv = (long long)BT * VV;
    float* logits = out;
    float* loss = nullptr;
    if ((long long)out_size > btv) {
        loss = out + btv;               // [logits..., loss]
    } else if ((long long)out_size < btv) {
        logits = fb;                    // loss-only output
        loss = out;
    }

    const long long llTH = (long long)TT * HH;
    const long long llTT2 = (long long)TT * TT;

    // 1) embeddings
    embed_k<<<BT, 256>>>(idx, tok, pos, x);

    // 2) Q/K/V projections: [4096,1024] @ [1024,1024]
    sgemm_k<false, false><<<dim3(HH / 128, BT / 128, 1), 256>>>(
        x, wq, nullptr, q, BT, HH, HH, 1.f, 0, 0, 0);
    sgemm_k<false, false><<<dim3(HH / 128, BT / 128, 1), 256>>>(
        x, wk, nullptr, k, BT, HH, HH, 1.f, 0, 0, 0);
    sgemm_k<false, false><<<dim3(HH / 128, BT / 128, 1), 256>>>(
        x, wv, nullptr, v, BT, HH, HH, 1.f, 0, 0, 0);

    // 3) scores = (Q @ K^T) * H^-0.5, per batch
    sgemm_k<true, false><<<dim3(TT / 128, TT / 128, BB), 256>>>(
        q, k, nullptr, s, TT, TT, HH, 0.03125f, llTH, llTH, llTT2);

    // 4) causal softmax
    softmax_causal_k<<<BT, 256>>>(s);

    // 5) attn out = P @ V, per batch
    sgemm_k<false, false><<<dim3(HH / 128, TT / 128, BB), 256>>>(
        s, v, nullptr, a, TT, HH, TT, 1.f, llTT2, llTH, llTH);

    // 6) MLP stack: Linear + LeakyReLU
    float* cur = a;
    float* nxt = b;
    for (int l = 0; l < LL; l++) {
        sgemm_k<false, true><<<dim3(HH / 128, BT / 128, 1), 256>>>(
            cur, hw + (long long)l * HH * HH, hb + (long long)l * HH, nxt,
            BT, HH, HH, 1.f, 0, 0, 0);
        float* t2 = cur; cur = nxt; nxt = t2;
    }

    // 7) lm_head: [4096,1024] @ [1024,32000] + lb
    sgemm_k<false, false><<<dim3(VV / 128, BT / 128, 1), 256>>>(
        cur, lw, lb, logits, BT, VV, HH, 1.f, 0, 0, 0);

    // 8) cross-entropy
    ce_row_k<<<BT, 256>>>(logits, tgt, rl);
    if (loss) loss_reduce_k<<<1, 256>>>(rl, loss);
}

// round 7
// speedup vs baseline: 3.0430x; 3.0430x over previous
#include <cuda_runtime.h>
#include <math.h>
#include <stdint.h>

// Fixed problem shape (SimpleLanguageModel_65498251264578)
#define BB 2
#define TT 2048
#define HH 1024
#define VV 32000
#define LL 4
#define BT (BB * TT)   // 4096

#define NEG_HUGE (-1e30f)   // finite -inf sentinel: avoids (-inf)-(-inf)=NaN in reductions

// ---------------------------------------------------------------------------
// mma.sync TF32 GEMM tile config
// ---------------------------------------------------------------------------
#define TMT 128          // CTA tile M
#define TNT 128          // CTA tile N
#define BK 16            // K per stage
#define NSTG 3           // pipeline stages
#define ROWF 20          // smem row stride in floats (pad 16 -> 20, conflict-free)
#define TILE_F (128 * ROWF)            // floats per (A or B) tile = 2560
#define STAGE_F (2 * TILE_F)           // 5120
#define SMEM_BYTES (NSTG * STAGE_F * 4)  // 61440

// ---------------------------------------------------------------------------
// Scratch (device globals — allocation-free rule)
// ---------------------------------------------------------------------------
__device__ __align__(128) float g_x[BT * HH];
__device__ __align__(128) float g_qkv[3 * BT * HH];     // q,k,v contiguous
__device__ __align__(128) float g_s[BB * TT * TT];      // scores / probs
__device__ __align__(128) float g_a[BT * HH];
__device__ __align__(128) float g_b[BT * HH];
__device__ __align__(128) float g_vT[BB * HH * TT];
__device__ __align__(128) float g_wT[3 * HH * HH];      // wqT,wkT,wvT
__device__ __align__(128) float g_hwT[LL * HH * HH];
__device__ __align__(128) float g_lwT[(long long)VV * HH];
__device__ __align__(128) float g_rowloss[BT];
__device__ __align__(128) float g_logits_fb[(long long)BT * VV];

// ---------------------------------------------------------------------------
// Helpers
// ---------------------------------------------------------------------------
__device__ __forceinline__ uint32_t s2u(const void* p) {
    uint32_t a;
    asm("{ .reg .u64 t; cvta.to.shared.u64 t, %1; cvt.u32.u64 %0, t; }"
        : "=r"(a) : "l"(p));
    return a;
}
__device__ __forceinline__ float rtf32(float x) {
    uint32_t u = __float_as_uint(x), o;
    asm("cvt.rna.tf32.f32 %0, %1;" : "=r"(o) : "r"(u));
    return __uint_as_float(o);
}
__device__ __forceinline__ void cp16(uint32_t dst, const void* src) {
    asm volatile("cp.async.ca.shared.global [%0], [%1], 16;" :: "r"(dst), "l"(src));
}
__device__ __forceinline__ void cp_commit() { asm volatile("cp.async.commit_group;"); }
__device__ __forceinline__ void cp_wait1() { asm volatile("cp.async.wait_group 1;"); }

__device__ __forceinline__ void mma_tf32(float* c, const uint32_t* a, const uint32_t* b) {
    asm volatile(
        "mma.sync.aligned.m16n8k8.row.col.f32.tf32.tf32.f32 "
        "{%0,%1,%2,%3}, {%4,%5,%6,%7}, {%8,%9}, {%0,%1,%2,%3};\n"
        : "+f"(c[0]), "+f"(c[1]), "+f"(c[2]), "+f"(c[3])
        : "r"(a[0]), "r"(a[1]), "r"(a[2]), "r"(a[3]), "r"(b[0]), "r"(b[1]));
}

// ---------------------------------------------------------------------------
// Embedding (tf32-rounded): x[b,t,:] = tok[idx[b,t],:] + pos[t,:]
// ---------------------------------------------------------------------------
__global__ void embed_k(const int* __restrict__ idx,
                        const float* __restrict__ tok,
                        const float* __restrict__ pos,
                        float* __restrict__ x) {
    int bt = blockIdx.x;
    int t = bt % TT;
    int v = idx[bt];
    const float* te = tok + (long long)v * HH;
    const float* pe = pos + (long long)t * HH;
    float* xo = x + (long long)bt * HH;
    for (int h = threadIdx.x; h < HH; h += blockDim.x)
        xo[h] = rtf32(te[h] + pe[h]);
}

// ---------------------------------------------------------------------------
// Transpose with tf32 rounding: out[C][R] = round(in[R][C]).  32x32 tiles.
// ---------------------------------------------------------------------------
__global__ void transpose_k(const float* __restrict__ in, float* __restrict__ out,
                            int R, int C, long long sIn, long long sOut) {
    __shared__ float t[32][33];
    in += (long long)blockIdx.z * sIn;
    out += (long long)blockIdx.z * sOut;
    int c0 = blockIdx.x * 32, r0 = blockIdx.y * 32;
    int tx = threadIdx.x, ty = threadIdx.y;   // 32 x 8
#pragma unroll
    for (int j = 0; j < 4; j++)
        t[ty + j * 8][tx] = in[(long long)(r0 + ty + j * 8) * C + c0 + tx];
    __syncthreads();
#pragma unroll
    for (int j = 0; j < 4; j++)
        out[(long long)(c0 + ty + j * 8) * R + r0 + tx] = rtf32(t[tx][ty + j * 8]);
}

// ---------------------------------------------------------------------------
// TF32 tensor-core NT GEMM: C[M,N] = act(alpha * A[M,K] @ B[N,K]^T + bias)
//   A, B row-major, K contiguous, pre-rounded to tf32.
//   M%128==0, N%128==0, K%16==0.
//   blockIdx.x = N tile, blockIdx.y = M tile, blockIdx.z = batch.
// ---------------------------------------------------------------------------
template <bool LEAKY, bool ROUND, bool BIAS>
__global__ void __launch_bounds__(256, 2) tgemm_k(
    const float* __restrict__ A, const float* __restrict__ B,
    const float* __restrict__ bias, float* __restrict__ C,
    int M, int N, int K, float alpha,
    long long sA, long long sB, long long sC) {
    extern __shared__ float sm[];
    const uint32_t sbase = s2u(sm);

    A += (long long)blockIdx.z * sA;
    B += (long long)blockIdx.z * sB;
    C += (long long)blockIdx.z * sC;
    const int m0 = blockIdx.y * TMT;
    const int n0 = blockIdx.x * TNT;
    const int tid = threadIdx.x;
    const int wid = tid >> 5;
    const int lane = tid & 31;
    const int wm = wid & 1;       // 2 warps along M  -> 64 rows each
    const int wn = wid >> 1;      // 4 warps along N  -> 32 cols each
    const int grp = lane >> 2;    // 0..7
    const int thr = lane & 3;     // 0..3
    const int NCH = K / BK;

    // loads: per tile 512 x 16B ops; 2 per thread per tile
    const int lrow0 = (0 * 256 + tid) >> 2, lc0 = (0 * 256 + tid) & 3;
    const int lrow1 = (1 * 256 + tid) >> 2, lc1 = (1 * 256 + tid) & 3;

    auto load_stage = [&](int ch, int s) {
        const float* Ab = A + (long long)ch * BK;
        const float* Bb = B + (long long)ch * BK;
        uint32_t st = sbase + s * (STAGE_F * 4);
        cp16(st + lrow0 * (ROWF * 4) + lc0 * 16,
             Ab + (long long)(m0 + lrow0) * K + lc0 * 4);
        cp16(st + lrow1 * (ROWF * 4) + lc1 * 16,
             Ab + (long long)(m0 + lrow1) * K + lc1 * 4);
        st += TILE_F * 4;
        cp16(st + lrow0 * (ROWF * 4) + lc0 * 16,
             Bb + (long long)(n0 + lrow0) * K + lc0 * 4);
        cp16(st + lrow1 * (ROWF * 4) + lc1 * 16,
             Bb + (long long)(n0 + lrow1) * K + lc1 * 4);
    };

    float acc[4][4][4];
#pragma unroll
    for (int mi = 0; mi < 4; mi++)
#pragma unroll
        for (int ni = 0; ni < 4; ni++)
#pragma unroll
            for (int r = 0; r < 4; r++) acc[mi][ni][r] = 0.f;

    // prologue: 2 stages in flight
    load_stage(0, 0); cp_commit();
    if (NCH > 1) { load_stage(1, 1); }
    cp_commit();

    for (int c = 0; c < NCH; c++) {
        const int s = c % NSTG;
        cp_wait1();
        __syncthreads();
        if (c + 2 < NCH) load_stage(c + 2, (c + 2) % NSTG);
        cp_commit();

        const float* sA = sm + s * STAGE_F;
        const float* sB = sA + TILE_F;
#pragma unroll
        for (int kk = 0; kk < 2; kk++) {
            const int k0 = kk * 8;
            uint32_t af[4][4], bf[4][2];
#pragma unroll
            for (int mi = 0; mi < 4; mi++) {
                const float* ap = sA + (wm * 64 + mi * 16 + grp) * ROWF + k0 + thr;
                af[mi][0] = __float_as_uint(ap[0]);
                af[mi][1] = __float_as_uint(ap[8 * ROWF]);
                af[mi][2] = __float_as_uint(ap[4]);
                af[mi][3] = __float_as_uint(ap[8 * ROWF + 4]);
            }
#pragma unroll
            for (int ni = 0; ni < 4; ni++) {
                const float* bp = sB + (wn * 32 + ni * 8 + grp) * ROWF + k0 + thr;
                bf[ni][0] = __float_as_uint(bp[0]);
                bf[ni][1] = __float_as_uint(bp[4]);
            }
#pragma unroll
            for (int mi = 0; mi < 4; mi++)
#pragma unroll
                for (int ni = 0; ni < 4; ni++)
                    mma_tf32(acc[mi][ni], af[mi], bf[ni]);
        }
        __syncthreads();
    }

    // epilogue: direct stores (two float2 per mma tile per thread)
#pragma unroll
    for (int mi = 0; mi < 4; mi++) {
#pragma unroll
        for (int ni = 0; ni < 4; ni++) {
            const int n = n0 + wn * 32 + ni * 8 + thr * 2;
            float b0 = 0.f, b1 = 0.f;
            if (BIAS) { b0 = __ldg(&bias[n]); b1 = __ldg(&bias[n + 1]); }
#pragma unroll
            for (int h = 0; h < 2; h++) {
                const int m = m0 + wm * 64 + mi * 16 + grp + h * 8;
                float v0 = acc[mi][ni][2 * h + 0] * alpha;
                float v1 = acc[mi][ni][2 * h + 1] * alpha;
                if (BIAS) { v0 += b0; v1 += b1; }
                if (LEAKY) {
                    v0 = (v0 >= 0.f) ? v0 : 0.01f * v0;
                    v1 = (v1 >= 0.f) ? v1 : 0.01f * v1;
                }
                if (ROUND) { v0 = rtf32(v0); v1 = rtf32(v1); }
                *(float2*)(C + (long long)m * N + n) = make_float2(v0, v1);
            }
        }
    }
}

// ---------------------------------------------------------------------------
// Merged max/sum block reduction.  All inputs use finite sentinel NEG_HUGE,
// never -inf, so m - M is always finite (no exp(NaN)).
// ---------------------------------------------------------------------------
__device__ __forceinline__ void blk_ms(float& m, float& s, float* rm, float* rs) {
    int tid = threadIdx.x;
    rm[tid] = m; rs[tid] = s;
    __syncthreads();
    for (int o = 128; o > 0; o >>= 1) {
        if (tid < o) {
            float m2 = rm[tid + o], s2 = rs[tid + o];
            float M = fmaxf(rm[tid], m2);
            rs[tid] = rs[tid] * expf(rm[tid] - M) + s2 * expf(m2 - M);
            rm[tid] = M;
        }
        __syncthreads();
    }
    m = rm[0]; s = rs[0];
    __syncthreads();
}

// Causal softmax in-place; probs tf32-rounded (they feed the PV GEMM).
__global__ void softmax_causal_k(float* __restrict__ sc) {
    __shared__ float rm[256], rs[256];
    long long row = blockIdx.x;
    int r = (int)(row % TT);
    float* p = sc + row * (long long)TT;
    int n = r + 1;
    int tid = threadIdx.x;

    float m = NEG_HUGE, s = 0.f;
    for (int j = tid; j < n; j += 256) {
        float v = p[j];
        if (v > m) { s = s * expf(m - v) + 1.f; m = v; }
        else s += expf(v - m);
    }
    blk_ms(m, s, rm, rs);
    float inv = 1.f / s;

    for (int j = tid; j < n; j += 256) p[j] = rtf32(expf(p[j] - m) * inv);
    for (int j = n + tid; j < TT; j += 256) p[j] = 0.f;
}

// ---------------------------------------------------------------------------
// Cross entropy (single online pass)
// ---------------------------------------------------------------------------
__global__ void ce_row_k(const float* __restrict__ logits,
                         const int* __restrict__ targets,
                         float* __restrict__ rowloss) {
    __shared__ float rm[256], rs[256];
    int row = blockIdx.x;
    const float* p = logits + (long long)row * VV;
    int tid = threadIdx.x;

    float m = NEG_HUGE, s = 0.f;
    for (int j = tid; j < VV; j += 256) {
        float v = p[j];
        if (v > m) { s = s * expf(m - v) + 1.f; m = v; }
        else s += expf(v - m);
    }
    blk_ms(m, s, rm, rs);

    if (tid == 0)
        rowloss[row] = m + logf(s) - p[targets[row]];
}

__global__ void loss_reduce_k(const float* __restrict__ rowloss,
                              float* __restrict__ out) {
    __shared__ float red[256];
    int tid = threadIdx.x;
    float s = 0.f;
    for (int j = tid; j < BT; j += 256) s += rowloss[j];
    red[tid] = s; __syncthreads();
    for (int o = 128; o > 0; o >>= 1) {
        if (tid < o) red[tid] += red[tid + o];
        __syncthreads();
    }
    if (tid == 0) out[0] = red[0] / (float)BT;
}

// ---------------------------------------------------------------------------
// Launch
// ---------------------------------------------------------------------------
extern "C" void kernel_launch(void* const* d_in, const int* in_sizes, int n_in,
                              void* d_out, int out_size) {
    const int* idx = (const int*)d_in[0];
    const int* tgt = (const int*)d_in[1];
    const float* tok = (const float*)d_in[2];
    const float* pos = (const float*)d_in[3];
    const float* wq = (const float*)d_in[4];
    const float* wk = (const float*)d_in[5];
    const float* wv = (const float*)d_in[6];
    const float* hw = (const float*)d_in[7];
    const float* hb = (const float*)d_in[8];
    const float* lw = (const float*)d_in[9];
    const float* lb = (const float*)d_in[10];

    float *x, *qkv, *s, *a, *b, *vT, *wT, *hwT, *lwT, *rl, *fb;
    cudaGetSymbolAddress((void**)&x, g_x);
    cudaGetSymbolAddress((void**)&qkv, g_qkv);
    cudaGetSymbolAddress((void**)&s, g_s);
    cudaGetSymbolAddress((void**)&a, g_a);
    cudaGetSymbolAddress((void**)&b, g_b);
    cudaGetSymbolAddress((void**)&vT, g_vT);
    cudaGetSymbolAddress((void**)&wT, g_wT);
    cudaGetSymbolAddress((void**)&hwT, g_hwT);
    cudaGetSymbolAddress((void**)&lwT, g_lwT);
    cudaGetSymbolAddress((void**)&rl, g_rowloss);
    cudaGetSymbolAddress((void**)&fb, g_logits_fb);

    cudaFuncSetAttribute(tgemm_k<false, true, false>,
                         cudaFuncAttributeMaxDynamicSharedMemorySize, SMEM_BYTES);
    cudaFuncSetAttribute(tgemm_k<false, false, false>,
                         cudaFuncAttributeMaxDynamicSharedMemorySize, SMEM_BYTES);
    cudaFuncSetAttribute(tgemm_k<true, true, true>,
                         cudaFuncAttributeMaxDynamicSharedMemorySize, SMEM_BYTES);
    cudaFuncSetAttribute(tgemm_k<false, false, true>,
                         cudaFuncAttributeMaxDynamicSharedMemorySize, SMEM_BYTES);

    float* out = (float*)d_out;
    const long long btv = (long long)BT * VV;
    float* logits = out;
    float* loss = nullptr;
    if ((long long)out_size > btv) {
        loss = out + btv;
    } else if ((long long)out_size < btv) {
        logits = fb;
        loss = out;
    }

    float* q = qkv;
    float* kk = qkv + (long long)BT * HH;
    float* v = qkv + 2LL * BT * HH;
    const long long llTH = (long long)TT * HH;
    const long long llTT2 = (long long)TT * TT;
    const long long llHH2 = (long long)HH * HH;

    // 0) weight transposes (tf32-rounded)
    transpose_k<<<dim3(HH / 32, HH / 32, 1), dim3(32, 8)>>>(wq, wT, HH, HH, 0, 0);
    transpose_k<<<dim3(HH / 32, HH / 32, 1), dim3(32, 8)>>>(wk, wT + llHH2, HH, HH, 0, 0);
    transpose_k<<<dim3(HH / 32, HH / 32, 1), dim3(32, 8)>>>(wv, wT + 2 * llHH2, HH, HH, 0, 0);
    transpose_k<<<dim3(HH / 32, HH / 32, LL), dim3(32, 8)>>>(hw, hwT, HH, HH, llHH2, llHH2);
    transpose_k<<<dim3(VV / 32, HH / 32, 1), dim3(32, 8)>>>(lw, lwT, HH, VV, 0, 0);

    // 1) embeddings
    embed_k<<<BT, 256>>>(idx, tok, pos, x);

    // 2) fused QKV (z batches the 3 weight matrices, A shared via sA=0)
    tgemm_k<false, true, false><<<dim3(HH / TNT, BT / TMT, 3), 256, SMEM_BYTES>>>(
        x, wT, nullptr, qkv, BT, HH, HH, 1.f, 0, llHH2, (long long)BT * HH);

    // 3) V transpose per batch
    transpose_k<<<dim3(HH / 32, TT / 32, BB), dim3(32, 8)>>>(v, vT, TT, HH, llTH, llTH);

    // 4) scores = (Q @ K^T) / 32
    tgemm_k<false, false, false><<<dim3(TT / TNT, TT / TMT, BB), 256, SMEM_BYTES>>>(
        q, kk, nullptr, s, TT, TT, HH, 0.03125f, llTH, llTH, llTT2);

    // 5) causal softmax
    softmax_causal_k<<<BT, 256>>>(s);

    // 6) attn out = P @ V
    tgemm_k<false, true, false><<<dim3(HH / TNT, TT / TMT, BB), 256, SMEM_BYTES>>>(
        s, vT, nullptr, a, TT, HH, TT, 1.f, llTT2, llTH, llTH);

    // 7) MLP stack
    float* cur = a;
    float* nxt = b;
    for (int l = 0; l < LL; l++) {
        tgemm_k<true, true, true><<<dim3(HH / TNT, BT / TMT, 1), 256, SMEM_BYTES>>>(
            cur, hwT + (long long)l * llHH2, hb + (long long)l * HH, nxt,
            BT, HH, HH, 1.f, 0, 0, 0);
        float* t2 = cur; cur = nxt; nxt = t2;
    }

    // 8) lm_head
    tgemm_k<false, false, true><<<dim3(VV / TNT, BT / TMT, 1), 256, SMEM_BYTES>>>(
        cur, lwT, lb, logits, BT, VV, HH, 1.f, 0, 0, 0);

    // 9) cross-entropy
    ce_row_k<<<BT, 256>>>(logits, tgt, rl);
    if (loss) loss_reduce_k<<<1, 256>>>(rl, loss);
}